// round 13
// baseline (speedup 1.0000x reference)
#include <cuda_runtime.h>
#include <cuda_fp16.h>
#include <cstdint>

// SinkhornDistance: B=64, N=M=1024, eps=0.1, 50 iterations.
// Scaling domain: K = exp(-C/eps); a = (mu+1e-8)/(K b); b = (nu+1e-8)/(K^T a)
// pi = exp(-C/eps) * a_i * b_j (fp32) ; cost_b = sum pi*C.  b0 = 1 (scale-inv).
//
// R13 = R12 with the team barrier halved: 32 blocks/team (RPB=32, 512-thread
// blocks, 64KB smem tile, 3 blocks/SM = 48 warps/SM unchanged) and all-thread
// acquire-spin detection (no tid0 spin + syncthreads broadcast).

#define BATCH 64
#define NN 1024
#define INV_EPS 10.0f
#define LOGEPS 1e-8f
#define MAX_ITER 50
#define ASCALE 4096.0f       // 2^12, exact; cancels in b = nu*ASCALE/T_scaled

#define RPB 32               // rows per block
#define BPB 32               // blocks per team (= NN/RPB)
#define THREADS 512

// Scratch (static device globals; no runtime allocation)
__device__ float g_T[3][BATCH * NN];     // rotation buffers (scaled col sums)
__device__ unsigned g_cnt[BATCH];        // arrival counters (monotonic)

__device__ __forceinline__ unsigned ld_acq(const unsigned* p) {
    unsigned v;
    asm volatile("ld.acquire.gpu.b32 %0, [%1];" : "=r"(v) : "l"(p) : "memory");
    return v;
}

// ---------------------------------------------------------------------------
// Zero T[0] (all batches), cost, counters. grid = 64 x 256.
__global__ void k_init(float* __restrict__ cost) {
    int idx = blockIdx.x * 256 + threadIdx.x;  // 16384 float4 = 64K floats
    ((float4*)g_T[0])[idx] = make_float4(0.f, 0.f, 0.f, 0.f);
    if (blockIdx.x == 0 && threadIdx.x < BATCH) {
        cost[threadIdx.x] = 0.0f;
        g_cnt[threadIdx.x] = 0u;
    }
}

// ---------------------------------------------------------------------------
__global__ void __launch_bounds__(THREADS, 3) sinkhorn_resident(
    const float* __restrict__ mu, const float* __restrict__ nu,
    const float* __restrict__ C, float* __restrict__ cost,
    float* __restrict__ pi, int teams)
{
    const int team = blockIdx.x / BPB;
    const int blk  = blockIdx.x % BPB;
    const int r0   = blk * RPB;
    const int tid  = threadIdx.x;
    const int lane = tid & 31, warp = tid >> 5;
    const int col4 = tid & 255;          // column group (4 cols)
    const int half = tid >> 8;           // 0: rows r0..r0+15, 1: +16
    const int w8   = warp & 7;           // warp index within the half

    // Paired-row K tile: ktile2[half*8+r2][col4] = rows (rbase+2r2, +1).
    __shared__ uint4 ktile2[RPB / 2][256];   // 64 KB
    __shared__ float mush[RPB];
    __shared__ float atrue[RPB];             // true a (epilogue)
    __shared__ uint32_t ash2[RPB];           // packed half2(a*ASCALE)
    __shared__ float wsum[RPB][9];           // padded

    for (int batch = team; batch < BATCH; batch += teams) {
        // ---- round setup: mu, nu, and the smem-resident K tile from C ----
        if (tid < RPB) mush[tid] = mu[(size_t)batch * NN + r0 + tid] + LOGEPS;
        float4 nv = ((const float4*)(nu + (size_t)batch * NN))[col4];
        nv.x = (nv.x + LOGEPS) * ASCALE;
        nv.y = (nv.y + LOGEPS) * ASCALE;
        nv.z = (nv.z + LOGEPS) * ASCALE;
        nv.w = (nv.w + LOGEPS) * ASCALE;

        const int rbase = r0 + half * 16;
#pragma unroll
        for (int r2 = 0; r2 < 8; r2++) {
            float4 c0 = ((const float4*)(C + ((size_t)batch * NN + rbase + 2 * r2) * NN))[col4];
            float4 c1 = ((const float4*)(C + ((size_t)batch * NN + rbase + 2 * r2 + 1) * NN))[col4];
            __half2 h00 = __floats2half2_rn(__expf(-c0.x * INV_EPS),
                                            __expf(-c0.y * INV_EPS));
            __half2 h01 = __floats2half2_rn(__expf(-c0.z * INV_EPS),
                                            __expf(-c0.w * INV_EPS));
            __half2 h10 = __floats2half2_rn(__expf(-c1.x * INV_EPS),
                                            __expf(-c1.y * INV_EPS));
            __half2 h11 = __floats2half2_rn(__expf(-c1.z * INV_EPS),
                                            __expf(-c1.w * INV_EPS));
            uint4 pk;
            pk.x = *(const unsigned*)&h00;
            pk.y = *(const unsigned*)&h01;
            pk.z = *(const unsigned*)&h10;
            pk.w = *(const unsigned*)&h11;
            ktile2[half * 8 + r2][col4] = pk;
        }

        unsigned* cntp = &g_cnt[batch];

        // ---- 50 iterations, dataflow-synced across the 32-block team ----
        for (int it = 0; it < MAX_ITER; it++) {
            if (it > 0) {
                // All-thread acquire spin: no barrier, per-thread ordering.
                unsigned target = (unsigned)(BPB * it);
                while (ld_acq(cntp) < target) { }
            }

            // b at this thread's 4 columns (half2 for the phase-1 dot).
            __half2 bh01, bh23;
            if (it == 0) {
                bh01 = __floats2half2_rn(1.f, 1.f);
                bh23 = bh01;
            } else {
                float4 t = ((const float4*)&g_T[(it + 2) % 3][(size_t)batch * NN])[col4];
                bh01 = __floats2half2_rn(__fdividef(nv.x, t.x),
                                         __fdividef(nv.y, t.y));
                bh23 = __floats2half2_rn(__fdividef(nv.z, t.z),
                                         __fdividef(nv.w, t.w));
            }

            // Zero-ahead: T[(it+1)%3] has no remaining readers. Race-free.
            if (blk == 0 && half == 0)
                ((float4*)&g_T[(it + 1) % 3][(size_t)batch * NN])[col4] =
                    make_float4(0.f, 0.f, 0.f, 0.f);

            // Phase 1: row dots for this half's 16 rows (8 LDS.128).
            float part[16];
#pragma unroll
            for (int r2 = 0; r2 < 8; r2++) {
                uint4 kv = ktile2[half * 8 + r2][col4];
                __half2 p0 = __hfma2(*(__half2*)&kv.y, bh23,
                                     __hmul2(*(__half2*)&kv.x, bh01));
                __half2 p1 = __hfma2(*(__half2*)&kv.w, bh23,
                                     __hmul2(*(__half2*)&kv.z, bh01));
                float2 f0 = __half22float2(p0);
                float2 f1 = __half22float2(p1);
                part[2 * r2]     = f0.x + f0.y;
                part[2 * r2 + 1] = f1.x + f1.y;
            }

            // Folded multi-row warp reduce: 31 shfl for 16 rows.
#pragma unroll
            for (int r = 0; r < 16; r++)
                part[r] += __shfl_xor_sync(0xffffffffu, part[r], 16);
            float u8[8];
#pragma unroll
            for (int j = 0; j < 8; j++) {
                u8[j] = (lane & 16) ? part[j + 8] : part[j];
                u8[j] += __shfl_xor_sync(0xffffffffu, u8[j], 8);
            }
            float u4[4];
#pragma unroll
            for (int j = 0; j < 4; j++) {
                u4[j] = (lane & 8) ? u8[j + 4] : u8[j];
                u4[j] += __shfl_xor_sync(0xffffffffu, u4[j], 4);
            }
            float u2[2];
#pragma unroll
            for (int j = 0; j < 2; j++) {
                u2[j] = (lane & 4) ? u4[j + 2] : u4[j];
                u2[j] += __shfl_xor_sync(0xffffffffu, u2[j], 2);
            }
            float q = (lane & 2) ? u2[1] : u2[0];
            q += __shfl_xor_sync(0xffffffffu, q, 1);
            int R = (lane >> 1) & 15;
            if (!(lane & 1)) wsum[half * 16 + R][w8] = q;
            __syncthreads();

            // Tiny critical section: smem-only + fast divide (32 rows).
            if (tid < RPB) {
                float s = 0.f;
#pragma unroll
                for (int w = 0; w < 8; w++) s += wsum[tid][w];
                float a = __fdividef(mush[tid], s);
                atrue[tid] = a;
                __half2 ah = __float2half2_rn(a * ASCALE);
                ash2[tid] = *(const uint32_t*)&ah;
            }
            __syncthreads();

            // Phase 2: scaled half2 column partials for this half's 16 rows.
            __half2 acc01 = __floats2half2_rn(0.f, 0.f);
            __half2 acc23 = acc01;
#pragma unroll
            for (int r2 = 0; r2 < 8; r2++) {
                uint4 kv = ktile2[half * 8 + r2][col4];
                uint32_t a0u = ash2[half * 16 + 2 * r2];
                uint32_t a1u = ash2[half * 16 + 2 * r2 + 1];
                __half2 a0 = *(const __half2*)&a0u;
                __half2 a1 = *(const __half2*)&a1u;
                acc01 = __hfma2(*(__half2*)&kv.x, a0, acc01);
                acc23 = __hfma2(*(__half2*)&kv.y, a0, acc23);
                acc01 = __hfma2(*(__half2*)&kv.z, a1, acc01);
                acc23 = __hfma2(*(__half2*)&kv.w, a1, acc23);
            }
            float2 a01 = __half22float2(acc01);
            float2 a23 = __half22float2(acc23);
            atomicAdd((float4*)(&g_T[it % 3][(size_t)batch * NN] + col4 * 4),
                      make_float4(a01.x, a01.y, a23.x, a23.y));

            // Arrive: fence -> monotonic counter (proven protocol from R10).
            __syncthreads();
            if (tid == 0) {
                __threadfence();
                atomicAdd(cntp, 1u);
            }
        }

        // ---- epilogue for this batch (needs all final T contributions) ----
        {
            unsigned target = (unsigned)(BPB * MAX_ITER);
            while (ld_acq(cntp) < target) { }
        }

        float4 t = ((const float4*)&g_T[(MAX_ITER - 1) % 3][(size_t)batch * NN])[col4];
        float4 bv;
        bv.x = nv.x / t.x;
        bv.y = nv.y / t.y;
        bv.z = nv.z / t.z;
        bv.w = nv.w / t.w;

        float cacc = 0.0f;
#pragma unroll
        for (int r = 0; r < 16; r++) {
            float a = atrue[half * 16 + r];
            float4 cv = ((const float4*)(C + ((size_t)batch * NN + rbase + r) * NN))[col4];
            float4 p;
            p.x = __expf(-cv.x * INV_EPS) * a * bv.x;
            p.y = __expf(-cv.y * INV_EPS) * a * bv.y;
            p.z = __expf(-cv.z * INV_EPS) * a * bv.z;
            p.w = __expf(-cv.w * INV_EPS) * a * bv.w;
            cacc += p.x * cv.x + p.y * cv.y + p.z * cv.z + p.w * cv.w;
            ((float4*)(pi + ((size_t)batch * NN + rbase + r) * NN))[col4] = p;
        }
#pragma unroll
        for (int o = 16; o; o >>= 1)
            cacc += __shfl_xor_sync(0xffffffffu, cacc, o);
        if (lane == 0) wsum[warp][0] = cacc;
        __syncthreads();
        if (tid == 0) {
            float s = 0.f;
#pragma unroll
            for (int w = 0; w < 16; w++) s += wsum[w][0];
            atomicAdd(&cost[batch], s);
        }
        __syncthreads();   // protect smem reuse in the next round
    }
}

// ---------------------------------------------------------------------------
extern "C" void kernel_launch(void* const* d_in, const int* in_sizes, int n_in,
                              void* d_out, int out_size) {
    const float* mu = (const float*)d_in[0];
    const float* nu = (const float*)d_in[1];
    const float* C  = (const float*)d_in[2];
    float* cost = (float*)d_out;                 // outputs: (cost[64], pi[64M])
    float* pi   = (float*)d_out + BATCH;

    // Co-residency-safe grid size (pure queries; deterministic per machine).
    int occ = 0, sms = 0, dev = 0;
    cudaGetDevice(&dev);
    cudaOccupancyMaxActiveBlocksPerMultiprocessor(&occ, sinkhorn_resident,
                                                  THREADS, 0);
    cudaDeviceGetAttribute(&sms, cudaDevAttrMultiProcessorCount, dev);
    int teams = (occ * sms) / BPB;
    if (teams > BATCH) teams = BATCH;
    if (teams < 1) teams = 1;

    k_init<<<64, 256>>>(cost);
    sinkhorn_resident<<<teams * BPB, THREADS>>>(mu, nu, C, cost, pi, teams);
}

// round 14
// speedup vs baseline: 3.5643x; 3.5643x over previous
#include <cuda_runtime.h>
#include <cuda_fp16.h>
#include <cstdint>

// SinkhornDistance: B=64, N=M=1024, eps=0.1, 50 iterations.
// Scaling domain: K = exp(-C/eps); a = (mu+1e-8)/(K b); b = (nu+1e-8)/(K^T a)
// pi = exp(-C/eps) * a_i * b_j (fp32) ; cost_b = sum pi*C.  b0 = 1 (scale-inv).
//
// R14 = R13's 32-block/512-thread teams, but with the PROVEN spin protocol
// (tid0-only acquire spin + __syncthreads broadcast). Isolates the barrier-
// width variable that R13 conflated with the all-thread-spin regression.

#define BATCH 64
#define NN 1024
#define INV_EPS 10.0f
#define LOGEPS 1e-8f
#define MAX_ITER 50
#define ASCALE 4096.0f       // 2^12, exact; cancels in b = nu*ASCALE/T_scaled

#define RPB 32               // rows per block
#define BPB 32               // blocks per team (= NN/RPB)
#define THREADS 512

// Scratch (static device globals; no runtime allocation)
__device__ float g_T[3][BATCH * NN];     // rotation buffers (scaled col sums)
__device__ unsigned g_cnt[BATCH];        // arrival counters (monotonic)

__device__ __forceinline__ unsigned ld_acq(const unsigned* p) {
    unsigned v;
    asm volatile("ld.acquire.gpu.b32 %0, [%1];" : "=r"(v) : "l"(p) : "memory");
    return v;
}

// ---------------------------------------------------------------------------
// Zero T[0] (all batches), cost, counters. grid = 64 x 256.
__global__ void k_init(float* __restrict__ cost) {
    int idx = blockIdx.x * 256 + threadIdx.x;  // 16384 float4 = 64K floats
    ((float4*)g_T[0])[idx] = make_float4(0.f, 0.f, 0.f, 0.f);
    if (blockIdx.x == 0 && threadIdx.x < BATCH) {
        cost[threadIdx.x] = 0.0f;
        g_cnt[threadIdx.x] = 0u;
    }
}

// ---------------------------------------------------------------------------
__global__ void __launch_bounds__(THREADS, 3) sinkhorn_resident(
    const float* __restrict__ mu, const float* __restrict__ nu,
    const float* __restrict__ C, float* __restrict__ cost,
    float* __restrict__ pi, int teams)
{
    const int team = blockIdx.x / BPB;
    const int blk  = blockIdx.x % BPB;
    const int r0   = blk * RPB;
    const int tid  = threadIdx.x;
    const int lane = tid & 31, warp = tid >> 5;
    const int col4 = tid & 255;          // column group (4 cols)
    const int half = tid >> 8;           // 0: rows r0..r0+15, 1: +16
    const int w8   = warp & 7;           // warp index within the half

    // Paired-row K tile: ktile2[half*8+r2][col4] = rows (rbase+2r2, +1).
    __shared__ uint4 ktile2[RPB / 2][256];   // 64 KB
    __shared__ float mush[RPB];
    __shared__ float atrue[RPB];             // true a (epilogue)
    __shared__ uint32_t ash2[RPB];           // packed half2(a*ASCALE)
    __shared__ float wsum[RPB][9];           // padded

    for (int batch = team; batch < BATCH; batch += teams) {
        // ---- round setup: mu, nu, and the smem-resident K tile from C ----
        if (tid < RPB) mush[tid] = mu[(size_t)batch * NN + r0 + tid] + LOGEPS;
        float4 nv = ((const float4*)(nu + (size_t)batch * NN))[col4];
        nv.x = (nv.x + LOGEPS) * ASCALE;
        nv.y = (nv.y + LOGEPS) * ASCALE;
        nv.z = (nv.z + LOGEPS) * ASCALE;
        nv.w = (nv.w + LOGEPS) * ASCALE;

        const int rbase = r0 + half * 16;
#pragma unroll
        for (int r2 = 0; r2 < 8; r2++) {
            float4 c0 = ((const float4*)(C + ((size_t)batch * NN + rbase + 2 * r2) * NN))[col4];
            float4 c1 = ((const float4*)(C + ((size_t)batch * NN + rbase + 2 * r2 + 1) * NN))[col4];
            __half2 h00 = __floats2half2_rn(__expf(-c0.x * INV_EPS),
                                            __expf(-c0.y * INV_EPS));
            __half2 h01 = __floats2half2_rn(__expf(-c0.z * INV_EPS),
                                            __expf(-c0.w * INV_EPS));
            __half2 h10 = __floats2half2_rn(__expf(-c1.x * INV_EPS),
                                            __expf(-c1.y * INV_EPS));
            __half2 h11 = __floats2half2_rn(__expf(-c1.z * INV_EPS),
                                            __expf(-c1.w * INV_EPS));
            uint4 pk;
            pk.x = *(const unsigned*)&h00;
            pk.y = *(const unsigned*)&h01;
            pk.z = *(const unsigned*)&h10;
            pk.w = *(const unsigned*)&h11;
            ktile2[half * 8 + r2][col4] = pk;
        }

        unsigned* cntp = &g_cnt[batch];

        // ---- 50 iterations, dataflow-synced across the 32-block team ----
        for (int it = 0; it < MAX_ITER; it++) {
            if (it > 0) {
                // Proven protocol: ONE thread spins, barrier broadcasts.
                if (tid == 0) {
                    unsigned target = (unsigned)(BPB * it);
                    while (ld_acq(cntp) < target) { }
                }
                __syncthreads();
            }

            // b at this thread's 4 columns (half2 for the phase-1 dot).
            __half2 bh01, bh23;
            if (it == 0) {
                bh01 = __floats2half2_rn(1.f, 1.f);
                bh23 = bh01;
            } else {
                float4 t = ((const float4*)&g_T[(it + 2) % 3][(size_t)batch * NN])[col4];
                bh01 = __floats2half2_rn(__fdividef(nv.x, t.x),
                                         __fdividef(nv.y, t.y));
                bh23 = __floats2half2_rn(__fdividef(nv.z, t.z),
                                         __fdividef(nv.w, t.w));
            }

            // Zero-ahead: T[(it+1)%3] has no remaining readers. Race-free.
            if (blk == 0 && half == 0)
                ((float4*)&g_T[(it + 1) % 3][(size_t)batch * NN])[col4] =
                    make_float4(0.f, 0.f, 0.f, 0.f);

            // Phase 1: row dots for this half's 16 rows (8 LDS.128).
            float part[16];
#pragma unroll
            for (int r2 = 0; r2 < 8; r2++) {
                uint4 kv = ktile2[half * 8 + r2][col4];
                __half2 p0 = __hfma2(*(__half2*)&kv.y, bh23,
                                     __hmul2(*(__half2*)&kv.x, bh01));
                __half2 p1 = __hfma2(*(__half2*)&kv.w, bh23,
                                     __hmul2(*(__half2*)&kv.z, bh01));
                float2 f0 = __half22float2(p0);
                float2 f1 = __half22float2(p1);
                part[2 * r2]     = f0.x + f0.y;
                part[2 * r2 + 1] = f1.x + f1.y;
            }

            // Folded multi-row warp reduce: 31 shfl for 16 rows.
#pragma unroll
            for (int r = 0; r < 16; r++)
                part[r] += __shfl_xor_sync(0xffffffffu, part[r], 16);
            float u8[8];
#pragma unroll
            for (int j = 0; j < 8; j++) {
                u8[j] = (lane & 16) ? part[j + 8] : part[j];
                u8[j] += __shfl_xor_sync(0xffffffffu, u8[j], 8);
            }
            float u4[4];
#pragma unroll
            for (int j = 0; j < 4; j++) {
                u4[j] = (lane & 8) ? u8[j + 4] : u8[j];
                u4[j] += __shfl_xor_sync(0xffffffffu, u4[j], 4);
            }
            float u2[2];
#pragma unroll
            for (int j = 0; j < 2; j++) {
                u2[j] = (lane & 4) ? u4[j + 2] : u4[j];
                u2[j] += __shfl_xor_sync(0xffffffffu, u2[j], 2);
            }
            float q = (lane & 2) ? u2[1] : u2[0];
            q += __shfl_xor_sync(0xffffffffu, q, 1);
            int R = (lane >> 1) & 15;
            if (!(lane & 1)) wsum[half * 16 + R][w8] = q;
            __syncthreads();

            // Tiny critical section: smem-only + fast divide (32 rows).
            if (tid < RPB) {
                float s = 0.f;
#pragma unroll
                for (int w = 0; w < 8; w++) s += wsum[tid][w];
                float a = __fdividef(mush[tid], s);
                atrue[tid] = a;
                __half2 ah = __float2half2_rn(a * ASCALE);
                ash2[tid] = *(const uint32_t*)&ah;
            }
            __syncthreads();

            // Phase 2: scaled half2 column partials for this half's 16 rows.
            __half2 acc01 = __floats2half2_rn(0.f, 0.f);
            __half2 acc23 = acc01;
#pragma unroll
            for (int r2 = 0; r2 < 8; r2++) {
                uint4 kv = ktile2[half * 8 + r2][col4];
                uint32_t a0u = ash2[half * 16 + 2 * r2];
                uint32_t a1u = ash2[half * 16 + 2 * r2 + 1];
                __half2 a0 = *(const __half2*)&a0u;
                __half2 a1 = *(const __half2*)&a1u;
                acc01 = __hfma2(*(__half2*)&kv.x, a0, acc01);
                acc23 = __hfma2(*(__half2*)&kv.y, a0, acc23);
                acc01 = __hfma2(*(__half2*)&kv.z, a1, acc01);
                acc23 = __hfma2(*(__half2*)&kv.w, a1, acc23);
            }
            // Two halves both atomic (independent float4 adds, same as R12's
            // two blocks would have done; atomic count per epoch unchanged
            // at 512 per batch... per block: 2x256 -> same 512K total as R12).
            float2 a01 = __half22float2(acc01);
            float2 a23 = __half22float2(acc23);
            // Combine halves in smem first: reuse wsum area is too small;
            // use direct atomic per half (proven fine since R7).
            atomicAdd((float4*)(&g_T[it % 3][(size_t)batch * NN] + col4 * 4),
                      make_float4(a01.x, a01.y, a23.x, a23.y));

            // Arrive: fence -> monotonic counter (proven protocol).
            __syncthreads();
            if (tid == 0) {
                __threadfence();
                atomicAdd(cntp, 1u);
            }
        }

        // ---- epilogue for this batch (needs all final T contributions) ----
        if (tid == 0) {
            unsigned target = (unsigned)(BPB * MAX_ITER);
            while (ld_acq(cntp) < target) { }
        }
        __syncthreads();

        float4 t = ((const float4*)&g_T[(MAX_ITER - 1) % 3][(size_t)batch * NN])[col4];
        float4 bv;
        bv.x = nv.x / t.x;
        bv.y = nv.y / t.y;
        bv.z = nv.z / t.z;
        bv.w = nv.w / t.w;

        float cacc = 0.0f;
#pragma unroll
        for (int r = 0; r < 16; r++) {
            float a = atrue[half * 16 + r];
            float4 cv = ((const float4*)(C + ((size_t)batch * NN + rbase + r) * NN))[col4];
            float4 p;
            p.x = __expf(-cv.x * INV_EPS) * a * bv.x;
            p.y = __expf(-cv.y * INV_EPS) * a * bv.y;
            p.z = __expf(-cv.z * INV_EPS) * a * bv.z;
            p.w = __expf(-cv.w * INV_EPS) * a * bv.w;
            cacc += p.x * cv.x + p.y * cv.y + p.z * cv.z + p.w * cv.w;
            ((float4*)(pi + ((size_t)batch * NN + rbase + r) * NN))[col4] = p;
        }
#pragma unroll
        for (int o = 16; o; o >>= 1)
            cacc += __shfl_xor_sync(0xffffffffu, cacc, o);
        if (lane == 0) wsum[warp][0] = cacc;
        __syncthreads();
        if (tid == 0) {
            float s = 0.f;
#pragma unroll
            for (int w = 0; w < 16; w++) s += wsum[w][0];
            atomicAdd(&cost[batch], s);
        }
        __syncthreads();   // protect smem reuse in the next round
    }
}

// ---------------------------------------------------------------------------
extern "C" void kernel_launch(void* const* d_in, const int* in_sizes, int n_in,
                              void* d_out, int out_size) {
    const float* mu = (const float*)d_in[0];
    const float* nu = (const float*)d_in[1];
    const float* C  = (const float*)d_in[2];
    float* cost = (float*)d_out;                 // outputs: (cost[64], pi[64M])
    float* pi   = (float*)d_out + BATCH;

    // Co-residency-safe grid size (pure queries; deterministic per machine).
    int occ = 0, sms = 0, dev = 0;
    cudaGetDevice(&dev);
    cudaOccupancyMaxActiveBlocksPerMultiprocessor(&occ, sinkhorn_resident,
                                                  THREADS, 0);
    cudaDeviceGetAttribute(&sms, cudaDevAttrMultiProcessorCount, dev);
    int teams = (occ * sms) / BPB;
    if (teams > BATCH) teams = BATCH;
    if (teams < 1) teams = 1;

    k_init<<<64, 256>>>(cost);
    sinkhorn_resident<<<teams * BPB, THREADS>>>(mu, nu, C, cost, pi, teams);
}